// round 9
// baseline (speedup 1.0000x reference)
#include <cuda_runtime.h>
#include <math.h>

#define N_NODES 8192
#define F_IN 128
#define F_OUT 64
#define NEG_SLOPE 0.2f
#define VERY_SMALL 1000000000000.0f
#define SD_BLOCKS 128
#define ROWS_PER_SD_BLOCK (N_NODES / SD_BLOCKS)   // 64 (8 per warp)
#define SM_GRID 592                               // 4 CTAs x 148 SMs, persistent

__device__ float g_s[N_NODES];
__device__ float g_d[N_NODES];
__device__ float g_bmax[SD_BLOCKS];   // per-block max of d

// Kernel A: fused prep + sd + per-block d-max (unchanged from R8).
__global__ __launch_bounds__(256) void sd_kernel(const float* __restrict__ h,
                                                 const float* __restrict__ w,
                                                 const float* __restrict__ a) {
    __shared__ float sw[F_IN * 65];
    __shared__ float sa[F_IN];
    __shared__ float ws[F_IN];
    __shared__ float wd[F_IN];
    __shared__ float wmax[8];
    const int t = threadIdx.x;

    if (t < F_IN) sa[t] = a[t];
    const float4* w4 = reinterpret_cast<const float4*>(w);
    #pragma unroll
    for (int r = 0; r < 8; ++r) {
        int f = t + r * 256;
        float4 v = w4[f];
        int k = f >> 4;
        int j = (f & 15) * 4;
        float* dst = &sw[k * 65 + j];
        dst[0] = v.x; dst[1] = v.y; dst[2] = v.z; dst[3] = v.w;
    }
    __syncthreads();

    {
        int k = t & 127;
        const float* arow = sa + ((t >= 128) ? F_OUT : 0);
        const float* wrow = &sw[k * 65];
        float acc = 0.f;
        #pragma unroll
        for (int j = 0; j < F_OUT; ++j)
            acc += wrow[j] * arow[j];
        if (t < 128) ws[k] = acc; else wd[k] = acc;
    }
    __syncthreads();

    const int warp = t >> 5;
    const int lane = t & 31;
    const int base = blockIdx.x * ROWS_PER_SD_BLOCK + warp * 8;
    const float4 wsv = reinterpret_cast<const float4*>(ws)[lane];
    const float4 wdv = reinterpret_cast<const float4*>(wd)[lane];
    const float4* h4 = reinterpret_cast<const float4*>(h);

    float4 hv[8];
    #pragma unroll
    for (int r = 0; r < 8; ++r)
        hv[r] = h4[(size_t)(base + r) * (F_IN / 4) + lane];

    float s[8], d[8];
    #pragma unroll
    for (int r = 0; r < 8; ++r) {
        s[r] = hv[r].x * wsv.x + hv[r].y * wsv.y + hv[r].z * wsv.z + hv[r].w * wsv.w;
        d[r] = hv[r].x * wdv.x + hv[r].y * wdv.y + hv[r].z * wdv.z + hv[r].w * wdv.w;
    }
    #pragma unroll
    for (int o = 16; o > 0; o >>= 1) {
        #pragma unroll
        for (int r = 0; r < 8; ++r) {
            s[r] += __shfl_xor_sync(0xffffffffu, s[r], o);
            d[r] += __shfl_xor_sync(0xffffffffu, d[r], o);
        }
    }
    float dmax = -INFINITY;
    if (lane == 0) {
        #pragma unroll
        for (int r = 0; r < 8; ++r) {
            g_s[base + r] = s[r];
            g_d[base + r] = d[r];
            dmax = fmaxf(dmax, d[r]);
        }
        wmax[warp] = dmax;
    }
    __syncthreads();
    if (t == 0) {
        float m = wmax[0];
        #pragma unroll
        for (int k = 1; k < 8; ++k) m = fmaxf(m, wmax[k]);
        g_bmax[blockIdx.x] = m;
    }
}

__device__ __forceinline__ float block_reduce_sum(float v, float* red) {
    __syncthreads();   // safe reuse of red[] across loop iterations
    #pragma unroll
    for (int o = 16; o > 0; o >>= 1)
        v += __shfl_xor_sync(0xffffffffu, v, o);
    int warp = threadIdx.x >> 5;
    if ((threadIdx.x & 31) == 0) red[warp] = v;
    __syncthreads();
    if (warp == 0) {
        float x = (threadIdx.x < 8) ? red[threadIdx.x] : 0.f;
        #pragma unroll
        for (int o = 4; o > 0; o >>= 1)
            x += __shfl_xor_sync(0xffffffffu, x, o);
        if (threadIdx.x == 0) red[0] = x;
    }
    __syncthreads();
    return red[0];
}

// Kernel B: persistent CTAs (592), each loops over rows with stride 592.
// R7's proven per-row body (interleaved loads, register stash, one reduce)
// plus a zero-register prefetch.global.L2 of the NEXT row issued right
// before the reduce bubble, keeping DRAM busy through reduce+store and
// turning next row's demand loads into L2 hits.
__global__ __launch_bounds__(256) void softmax_kernel(const float* __restrict__ adj,
                                                      float* __restrict__ out) {
    __shared__ float red[8];
    const int t = threadIdx.x;
    const int lane = t & 31;

    // D fold: 128 bmax = 32 float4, one per lane, 5 shfls. Row-independent.
    float4 mm = __ldg(&reinterpret_cast<const float4*>(g_bmax)[lane]);
    float D = fmaxf(fmaxf(mm.x, mm.y), fmaxf(mm.z, mm.w));
    #pragma unroll
    for (int o = 16; o > 0; o >>= 1)
        D = fmaxf(D, __shfl_xor_sync(0xffffffffu, D, o));

    const float4* dp = reinterpret_cast<const float4*>(g_d);

    for (int i = blockIdx.x; i < N_NODES; i += SM_GRID) {
        const float si = g_s[i];
        float M = si + D;
        M = M >= 0.f ? M : NEG_SLOPE * M;

        const float4* ap = reinterpret_cast<const float4*>(adj + (size_t)i * N_NODES);

        float4 e[8];
        float lsum = 0.f;
        #pragma unroll
        for (int k = 0; k < 8; ++k) {
            const int c = t + k * 256;
            float4 av = __ldcs(&ap[c]);   // adj read once: evict-first
            float4 dv = __ldg(&dp[c]);    // 32 KB, reused: cached
            float v0 = si + dv.x; v0 = v0 >= 0.f ? v0 : NEG_SLOPE * v0; v0 = (av.x > 0.f) ? v0 : -VERY_SMALL;
            float v1 = si + dv.y; v1 = v1 >= 0.f ? v1 : NEG_SLOPE * v1; v1 = (av.y > 0.f) ? v1 : -VERY_SMALL;
            float v2 = si + dv.z; v2 = v2 >= 0.f ? v2 : NEG_SLOPE * v2; v2 = (av.z > 0.f) ? v2 : -VERY_SMALL;
            float v3 = si + dv.w; v3 = v3 >= 0.f ? v3 : NEG_SLOPE * v3; v3 = (av.w > 0.f) ? v3 : -VERY_SMALL;
            e[k].x = __expf(v0 - M);
            e[k].y = __expf(v1 - M);
            e[k].z = __expf(v2 - M);
            e[k].w = __expf(v3 - M);
            lsum += (e[k].x + e[k].y) + (e[k].z + e[k].w);
        }

        // Prefetch next row into L2 (zero register cost): 256 thr x 128 B = 32 KB.
        const int nxt = i + SM_GRID;
        if (nxt < N_NODES) {
            const char* np = reinterpret_cast<const char*>(adj + (size_t)nxt * N_NODES) + t * 128;
            asm volatile("prefetch.global.L2 [%0];" :: "l"(np));
        }

        const float inv = 1.0f / block_reduce_sum(lsum, red);

        float4* op = reinterpret_cast<float4*>(out + (size_t)i * N_NODES);
        #pragma unroll
        for (int k = 0; k < 8; ++k) {
            const int c = t + k * 256;
            float4 o = e[k];
            o.x *= inv; o.y *= inv; o.z *= inv; o.w *= inv;
            __stcs(&op[c], o);   // out never re-read: streaming store
        }
    }
}

extern "C" void kernel_launch(void* const* d_in, const int* in_sizes, int n_in,
                              void* d_out, int out_size) {
    const float* h   = (const float*)d_in[0];  // [8192,128]
    const float* adj = (const float*)d_in[1];  // [8192,8192]
    const float* w   = (const float*)d_in[2];  // [128,64]
    const float* a   = (const float*)d_in[3];  // [128,1]
    float* out = (float*)d_out;

    sd_kernel<<<SD_BLOCKS, 256>>>(h, w, a);
    softmax_kernel<<<SM_GRID, 256>>>(adj, out);
}

// round 10
// speedup vs baseline: 1.1033x; 1.1033x over previous
#include <cuda_runtime.h>
#include <math.h>

#define N_NODES 8192
#define F_IN 128
#define F_OUT 64
#define NEG_SLOPE 0.2f
#define VERY_SMALL 1000000000000.0f
#define SD_BLOCKS 128
#define ROWS_PER_SD_BLOCK (N_NODES / SD_BLOCKS)   // 64 (8 per warp)

__device__ float g_s[N_NODES];
__device__ float g_d[N_NODES];
__device__ float g_bmax[SD_BLOCKS];   // per-block max of d

// Kernel A: fused prep + sd + per-block d-max (R8 version).
__global__ __launch_bounds__(256) void sd_kernel(const float* __restrict__ h,
                                                 const float* __restrict__ w,
                                                 const float* __restrict__ a) {
    __shared__ float sw[F_IN * 65];
    __shared__ float sa[F_IN];
    __shared__ float ws[F_IN];
    __shared__ float wd[F_IN];
    __shared__ float wmax[8];
    const int t = threadIdx.x;

    if (t < F_IN) sa[t] = a[t];
    const float4* w4 = reinterpret_cast<const float4*>(w);
    #pragma unroll
    for (int r = 0; r < 8; ++r) {
        int f = t + r * 256;
        float4 v = w4[f];
        int k = f >> 4;
        int j = (f & 15) * 4;
        float* dst = &sw[k * 65 + j];
        dst[0] = v.x; dst[1] = v.y; dst[2] = v.z; dst[3] = v.w;
    }
    __syncthreads();

    {
        int k = t & 127;
        const float* arow = sa + ((t >= 128) ? F_OUT : 0);
        const float* wrow = &sw[k * 65];
        float acc = 0.f;
        #pragma unroll
        for (int j = 0; j < F_OUT; ++j)
            acc += wrow[j] * arow[j];
        if (t < 128) ws[k] = acc; else wd[k] = acc;
    }
    __syncthreads();

    const int warp = t >> 5;
    const int lane = t & 31;
    const int base = blockIdx.x * ROWS_PER_SD_BLOCK + warp * 8;
    const float4 wsv = reinterpret_cast<const float4*>(ws)[lane];
    const float4 wdv = reinterpret_cast<const float4*>(wd)[lane];
    const float4* h4 = reinterpret_cast<const float4*>(h);

    float4 hv[8];
    #pragma unroll
    for (int r = 0; r < 8; ++r)
        hv[r] = h4[(size_t)(base + r) * (F_IN / 4) + lane];

    float s[8], d[8];
    #pragma unroll
    for (int r = 0; r < 8; ++r) {
        s[r] = hv[r].x * wsv.x + hv[r].y * wsv.y + hv[r].z * wsv.z + hv[r].w * wsv.w;
        d[r] = hv[r].x * wdv.x + hv[r].y * wdv.y + hv[r].z * wdv.z + hv[r].w * wdv.w;
    }
    #pragma unroll
    for (int o = 16; o > 0; o >>= 1) {
        #pragma unroll
        for (int r = 0; r < 8; ++r) {
            s[r] += __shfl_xor_sync(0xffffffffu, s[r], o);
            d[r] += __shfl_xor_sync(0xffffffffu, d[r], o);
        }
    }
    float dmax = -INFINITY;
    if (lane == 0) {
        #pragma unroll
        for (int r = 0; r < 8; ++r) {
            g_s[base + r] = s[r];
            g_d[base + r] = d[r];
            dmax = fmaxf(dmax, d[r]);
        }
        wmax[warp] = dmax;
    }
    __syncthreads();
    if (t == 0) {
        float m = wmax[0];
        #pragma unroll
        for (int k = 1; k < 8; ++k) m = fmaxf(m, wmax[k]);
        g_bmax[blockIdx.x] = m;
    }
}

__device__ __forceinline__ float block_reduce_sum(float v, float* red) {
    #pragma unroll
    for (int o = 16; o > 0; o >>= 1)
        v += __shfl_xor_sync(0xffffffffu, v, o);
    int warp = threadIdx.x >> 5;
    if ((threadIdx.x & 31) == 0) red[warp] = v;
    __syncthreads();
    if (warp == 0) {
        float x = (threadIdx.x < 8) ? red[threadIdx.x] : 0.f;
        #pragma unroll
        for (int o = 4; o > 0; o >>= 1)
            x += __shfl_xor_sync(0xffffffffu, x, o);
        if (threadIdx.x == 0) red[0] = x;
    }
    __syncthreads();
    return red[0];
}

// Kernel B: R7 softmax body, unchanged, plus griddepcontrol.wait at the top
// so it can be pre-launched under sd_kernel via PDL.
__global__ __launch_bounds__(256) void softmax_kernel(const float* __restrict__ adj,
                                                      float* __restrict__ out) {
    __shared__ float red[8];
    const int i = blockIdx.x;
    const int t = threadIdx.x;
    const int lane = t & 31;

    // PDL: block until sd_kernel's writes (g_s/g_d/g_bmax) are visible.
    asm volatile("griddepcontrol.wait;" ::: "memory");

    const float si = g_s[i];

    // Warp-parallel D fold: 128 bmax = 32 float4, one per lane, 5 shfls.
    float4 mm = __ldg(&reinterpret_cast<const float4*>(g_bmax)[lane]);
    float D = fmaxf(fmaxf(mm.x, mm.y), fmaxf(mm.z, mm.w));
    #pragma unroll
    for (int o = 16; o > 0; o >>= 1)
        D = fmaxf(D, __shfl_xor_sync(0xffffffffu, D, o));
    float M = si + D;
    M = M >= 0.f ? M : NEG_SLOPE * M;

    const float4* ap = reinterpret_cast<const float4*>(adj + (size_t)i * N_NODES);
    const float4* dp = reinterpret_cast<const float4*>(g_d);

    float4 e[8];
    float lsum = 0.f;
    #pragma unroll
    for (int k = 0; k < 8; ++k) {
        const int c = t + k * 256;
        float4 av = __ldcs(&ap[c]);   // adj read once: evict-first
        float4 dv = __ldg(&dp[c]);    // 32 KB, reused by all CTAs: cached
        float v0 = si + dv.x; v0 = v0 >= 0.f ? v0 : NEG_SLOPE * v0; v0 = (av.x > 0.f) ? v0 : -VERY_SMALL;
        float v1 = si + dv.y; v1 = v1 >= 0.f ? v1 : NEG_SLOPE * v1; v1 = (av.y > 0.f) ? v1 : -VERY_SMALL;
        float v2 = si + dv.z; v2 = v2 >= 0.f ? v2 : NEG_SLOPE * v2; v2 = (av.z > 0.f) ? v2 : -VERY_SMALL;
        float v3 = si + dv.w; v3 = v3 >= 0.f ? v3 : NEG_SLOPE * v3; v3 = (av.w > 0.f) ? v3 : -VERY_SMALL;
        e[k].x = __expf(v0 - M);
        e[k].y = __expf(v1 - M);
        e[k].z = __expf(v2 - M);
        e[k].w = __expf(v3 - M);
        lsum += (e[k].x + e[k].y) + (e[k].z + e[k].w);
    }
    const float ssum = block_reduce_sum(lsum, red);
    const float inv = 1.0f / ssum;

    float4* op = reinterpret_cast<float4*>(out + (size_t)i * N_NODES);
    #pragma unroll
    for (int k = 0; k < 8; ++k) {
        const int c = t + k * 256;
        float4 o = e[k];
        o.x *= inv; o.y *= inv; o.z *= inv; o.w *= inv;
        __stcs(&op[c], o);   // out never re-read: streaming store
    }
}

extern "C" void kernel_launch(void* const* d_in, const int* in_sizes, int n_in,
                              void* d_out, int out_size) {
    const float* h   = (const float*)d_in[0];  // [8192,128]
    const float* adj = (const float*)d_in[1];  // [8192,8192]
    const float* w   = (const float*)d_in[2];  // [128,64]
    const float* a   = (const float*)d_in[3];  // [128,1]
    float* out = (float*)d_out;

    sd_kernel<<<SD_BLOCKS, 256>>>(h, w, a);

    // Launch softmax with programmatic dependent launch: its CTAs pre-launch
    // under sd_kernel and block at griddepcontrol.wait until sd completes.
    cudaLaunchConfig_t cfg = {};
    cfg.gridDim = dim3(N_NODES, 1, 1);
    cfg.blockDim = dim3(256, 1, 1);
    cfg.dynamicSmemBytes = 0;
    cudaLaunchAttribute attrs[1];
    attrs[0].id = cudaLaunchAttributeProgrammaticStreamSerialization;
    attrs[0].val.programmaticStreamSerializationAllowed = 1;
    cfg.attrs = attrs;
    cfg.numAttrs = 1;
    cudaLaunchKernelEx(&cfg, softmax_kernel, adj, out);
}